// round 8
// baseline (speedup 1.0000x reference)
#include <cuda_runtime.h>
#include <math.h>

#define B_    16
#define T_    128
#define V_    32000
#define H_    768
#define P_    384
#define NBOW_ 64
#define BT_   (B_ * T_)
#define EPS_  0.05f
#define TAU_  0.07f
#define CSH_  16.0f

// ---- scratch (__device__ globals; no allocation allowed) ----
__device__ float g_ce[BT_];
__device__ float g_vf[BT_];
__device__ float g_z [2 * B_ * P_];
__device__ float g_gram[B_ * B_];
__device__ float g_bce [B_];

// ============================================================
// K1: label-smoothed CE partials, fixed-shift LSE.
// grid = BT_, block = 256.
// ============================================================
__global__ void k_ce(const float* __restrict__ logits, const int* __restrict__ labels) {
    const int tok = blockIdx.x;
    const int tid = threadIdx.x;
    const float4* p = reinterpret_cast<const float4*>(logits + (size_t)tok * V_);

    float s0 = 0.f, s1 = 0.f, s2 = 0.f, s3 = 0.f;
    float t0 = 0.f, t1 = 0.f, t2 = 0.f, t3 = 0.f;
    #pragma unroll 4
    for (int i = tid; i < V_ / 4; i += 256) {
        float4 v = p[i];
        t0 += v.x; t1 += v.y; t2 += v.z; t3 += v.w;
        s0 += __expf(v.x - CSH_);
        s1 += __expf(v.y - CSH_);
        s2 += __expf(v.z - CSH_);
        s3 += __expf(v.w - CSH_);
    }
    float S = (s0 + s1) + (s2 + s3);
    float TS = (t0 + t1) + (t2 + t3);

    __shared__ float shs[256], sht[256];
    shs[tid] = S; sht[tid] = TS;
    __syncthreads();
    for (int off = 128; off > 0; off >>= 1) {
        if (tid < off) { shs[tid] += shs[tid + off]; sht[tid] += sht[tid + off]; }
        __syncthreads();
    }

    if (tid == 0) {
        float lse = CSH_ + logf(shs[0]);
        int lab = labels[tok];
        bool valid = (lab != 0) && (lab != -100);
        int lc = lab < 0 ? 0 : (lab >= V_ ? V_ - 1 : lab);
        float xl = logits[(size_t)tok * V_ + lc];
        float lp_lab = xl - lse;
        float lp_sum = sht[0] - (float)V_ * lse;
        float loss = -((1.0f - EPS_) * lp_lab + (EPS_ / (float)V_) * lp_sum);
        g_ce[tok] = valid ? loss : 0.0f;
        g_vf[tok] = valid ? 1.0f : 0.0f;
    }
}

// ---- 384-thread block sum ----
__device__ __forceinline__ float blockreduce384(float v, float* red, int tid) {
    red[tid] = v;
    __syncthreads();
    if (tid < 128) red[tid] += red[tid + 256];
    __syncthreads();
    for (int off = 128; off > 0; off >>= 1) {
        if (tid < off) red[tid] += red[tid + off];
        __syncthreads();
    }
    float r = red[0];
    __syncthreads();
    return r;
}

// ============================================================
// K2 (k_side): 48 blocks x 384 threads.
//   blocks 0..31  : fused [pool+]LN+GEMV1+GELU+GEMV2+l2norm -> g_z
//   blocks 32..47 : gram row b + BoW BCE row b  (b = bid-32)
// ============================================================
__global__ void k_side(const float* __restrict__ enc,
                       const float* __restrict__ dec, const int* __restrict__ mask,
                       const int* __restrict__ labels,
                       const float* __restrict__ Wb, const float* __restrict__ bb,
                       const float* __restrict__ g_e, const float* __restrict__ be_,
                       const float* __restrict__ W1e, const float* __restrict__ b1e,
                       const float* __restrict__ W2e, const float* __restrict__ b2e,
                       const float* __restrict__ g_t, const float* __restrict__ bt_,
                       const float* __restrict__ W1t, const float* __restrict__ b1t,
                       const float* __restrict__ W2t, const float* __restrict__ b2t) {
    const int bid = blockIdx.x;
    const int tid = threadIdx.x;

    if (bid < 2 * B_) {
        const bool is_e = bid < B_;
        const int row  = is_e ? bid : bid - B_;
        const float* g  = is_e ? g_e : g_t;
        const float* bn = is_e ? be_ : bt_;
        const float* W1 = is_e ? W1e : W1t;
        const float* b1 = is_e ? b1e : b1t;
        const float* W2 = is_e ? W2e : W2t;
        const float* b2 = is_e ? b2e : b2t;
        float* z = g_z + bid * P_;

        __shared__ float ln[H_];
        __shared__ float red[P_];
        __shared__ float h1s[P_];
        __shared__ float mk[T_];

        float a0, a1;
        if (is_e) {
            a0 = enc[row * H_ + tid];
            a1 = enc[row * H_ + tid + P_];
        } else {
            if (tid < T_) mk[tid] = (float)mask[row * T_ + tid];
            __syncthreads();
            if (tid == 0) {
                float s = 0.f;
                #pragma unroll
                for (int t = 0; t < T_; t++) s += mk[t];
                red[0] = 1.0f / fmaxf(s, 1.0f);
            }
            __syncthreads();
            float minv = red[0];
            const float* base = dec + (size_t)row * T_ * H_ + tid;
            float p0 = 0.f, p1 = 0.f, q0 = 0.f, q1 = 0.f;
            #pragma unroll 8
            for (int t = 0; t < T_; t += 2) {
                p0 = fmaf(base[(size_t)t * H_],            mk[t],     p0);
                q0 = fmaf(base[(size_t)t * H_ + P_],       mk[t],     q0);
                p1 = fmaf(base[(size_t)(t + 1) * H_],      mk[t + 1], p1);
                q1 = fmaf(base[(size_t)(t + 1) * H_ + P_], mk[t + 1], q1);
            }
            a0 = (p0 + p1) * minv;
            a1 = (q0 + q1) * minv;
            __syncthreads();
        }

        float mean = blockreduce384(a0 + a1, red, tid) * (1.0f / (float)H_);
        float d0 = a0 - mean, d1 = a1 - mean;
        float var = blockreduce384(d0 * d0 + d1 * d1, red, tid) * (1.0f / (float)H_);
        float inv = rsqrtf(var + 1e-5f);

        ln[tid]      = d0 * inv * g[tid]      + bn[tid];
        ln[tid + P_] = d1 * inv * g[tid + P_] + bn[tid + P_];
        __syncthreads();

        float acc = b1[tid];
        #pragma unroll 32
        for (int k = 0; k < H_; k++) acc = fmaf(ln[k], W1[k * P_ + tid], acc);
        h1s[tid] = 0.5f * acc * (1.0f + erff(acc * 0.70710678118654752f));
        __syncthreads();

        float acc2 = b2[tid];
        #pragma unroll 32
        for (int k = 0; k < P_; k++) acc2 = fmaf(h1s[k], W2[k * P_ + tid], acc2);

        float n2 = blockreduce384(acc2 * acc2, red, tid);
        float nrm = fmaxf(sqrtf(n2), 1e-12f);
        z[tid] = acc2 / nrm;
    } else {
        const int b = bid - 2 * B_;
        __shared__ float er_s[H_];
        __shared__ float gpart[256];
        __shared__ float bpart[128];
        __shared__ float term[NBOW_];
        __shared__ int   bow_hit[NBOW_];

        er_s[tid]       = enc[b * H_ + tid];
        er_s[tid + P_]  = enc[b * H_ + tid + P_];
        if (tid < NBOW_) bow_hit[tid] = 0;
        __syncthreads();

        if (tid < 256) {
            int j = tid >> 4, c = tid & 15;
            const float* a   = er_s + c * 48;
            const float* b2r = enc + j * H_ + c * 48;
            float acc = 0.0f;
            #pragma unroll
            for (int k = 0; k < 48; k++) acc = fmaf(a[k], b2r[k], acc);
            gpart[tid] = acc;
        } else {
            int t = tid - 256;
            {
                int lab = labels[b * T_ + t];
                bool valid = (lab != 0) && (lab != -100);
                int lc = lab < 0 ? 0 : (lab >= V_ ? V_ - 1 : lab);
                if (valid && (lc % 500 == 0)) {
                    int q = lc / 500;
                    if (q < NBOW_) bow_hit[q] = 1;
                }
            }
            int i = t & 63, h = t >> 6;
            const int k0 = h * 384;
            float acc = 0.0f;
            #pragma unroll 16
            for (int k = 0; k < 384; k++)
                acc = fmaf(er_s[k0 + k], Wb[(k0 + k) * NBOW_ + i], acc);
            bpart[t] = acc;
        }
        __syncthreads();

        if (tid < 16) {
            float s = 0.f;
            #pragma unroll
            for (int c = 0; c < 16; c++) s += gpart[tid * 16 + c];
            g_gram[b * 16 + tid] = s;
        } else if (tid >= 64 && tid < 128) {
            int i = tid - 64;
            float bl = bb[i] + bpart[i] + bpart[64 + i];
            float tt = (float)bow_hit[i];
            term[i] = fmaxf(bl, 0.0f) - bl * tt + log1pf(expf(-fabsf(bl)));
        }
        __syncthreads();
        if (tid < 32) {
            float v = term[tid] + term[tid + 32];
            #pragma unroll
            for (int off = 16; off > 0; off >>= 1) v += __shfl_down_sync(0xffffffffu, v, off);
            if (tid == 0) g_bce[b] = v;
        }
    }
}

// ============================================================
// K3 (k_final): 1 block x 1024 threads, static smem only.
// z_t half staged in smem (24KB); z_e read from global (L2).
// ============================================================
__global__ void k_final(const float* __restrict__ enc, float* __restrict__ out) {
    const int tid = threadIdx.x;
    __shared__ float zt_s[B_ * P_];          // 24KB
    __shared__ float red[1024];
    __shared__ float sim[256];
    __shared__ float rowloss[B_], colloss[B_];
    __shared__ float acc_terms[6];

    // stage z_t into smem
    #pragma unroll
    for (int k = tid; k < B_ * P_; k += 1024) zt_s[k] = g_z[B_ * P_ + k];

    // ---- CE reduce (2048 elems, 2 per thread) ----
    float a = g_ce[tid] + g_ce[tid + 1024];
    float w = g_vf[tid] + g_vf[tid + 1024];
    __syncthreads();
    red[tid] = a; __syncthreads();
    for (int off = 512; off > 0; off >>= 1) { if (tid < off) red[tid] += red[tid + off]; __syncthreads(); }
    if (tid == 0) acc_terms[0] = red[0];
    __syncthreads();
    red[tid] = w; __syncthreads();
    for (int off = 512; off > 0; off >>= 1) { if (tid < off) red[tid] += red[tid + off]; __syncthreads(); }
    if (tid == 0) acc_terms[1] = red[0];
    __syncthreads();

    // ---- sim: 256 pairs x 4 chunks of 96 ----
    {
        int p = tid >> 2, c = tid & 3;
        int i = p >> 4, j = p & 15;
        const float* ze = g_z + i * P_ + c * 96;
        const float* zt = zt_s + j * P_ + c * 96;
        float acc = 0.0f;
        #pragma unroll
        for (int k = 0; k < 96; k++) acc = fmaf(ze[k], zt[k], acc);
        red[tid] = acc;
    }
    __syncthreads();
    if (tid < 256)
        sim[tid] = (red[tid * 4] + red[tid * 4 + 1] + red[tid * 4 + 2] + red[tid * 4 + 3]) / TAU_;
    __syncthreads();

    // ---- align ----
    if (tid < B_) {
        float mx = -1e30f, mc = -1e30f;
        #pragma unroll
        for (int j = 0; j < B_; j++) { mx = fmaxf(mx, sim[tid * 16 + j]); mc = fmaxf(mc, sim[j * 16 + tid]); }
        float se = 0.f, sc = 0.f;
        #pragma unroll
        for (int j = 0; j < B_; j++) { se += expf(sim[tid * 16 + j] - mx); sc += expf(sim[j * 16 + tid] - mc); }
        rowloss[tid] = -(sim[tid * 16 + tid] - (mx + logf(se)));
        colloss[tid] = -(sim[tid * 16 + tid] - (mc + logf(sc)));
    }
    __syncthreads();
    if (tid == 0) {
        float li = 0.f, lj = 0.f;
        #pragma unroll
        for (int i = 0; i < B_; i++) { li += rowloss[i]; lj += colloss[i]; }
        acc_terms[2] = 0.5f * (li + lj) / (float)B_;
        float bs = 0.f;
        #pragma unroll
        for (int i = 0; i < B_; i++) bs += g_bce[i];
        acc_terms[3] = bs / (float)(B_ * NBOW_);
    }

    // ---- diversity from g_gram ----
    float dacc = 0.0f;
    if (tid < 256) {
        int i = tid >> 4, j = tid & 15;
        if (i != j) {
            float ni = fmaxf(sqrtf(g_gram[i * 16 + i]), 1e-12f);
            float nj = fmaxf(sqrtf(g_gram[j * 16 + j]), 1e-12f);
            dacc = fabsf(g_gram[i * 16 + j] / (ni * nj));
        }
    }
    __syncthreads();
    red[tid] = dacc; __syncthreads();
    for (int off = 512; off > 0; off >>= 1) { if (tid < off) red[tid] += red[tid + off]; __syncthreads(); }
    if (tid == 0) acc_terms[4] = red[0] / (float)(B_ * B_ - B_);
    __syncthreads();

    // ---- variance (ddof=1), one column per thread (tid < 768) ----
    float vacc = 0.0f;
    if (tid < H_) {
        float mu = 0.0f;
        #pragma unroll
        for (int b = 0; b < B_; b++) mu += enc[b * H_ + tid];
        mu *= (1.0f / (float)B_);
        float ss = 0.0f;
        #pragma unroll
        for (int b = 0; b < B_; b++) { float d = enc[b * H_ + tid] - mu; ss += d * d; }
        vacc = expf(-(ss * (1.0f / (float)(B_ - 1))));
    }
    __syncthreads();
    red[tid] = vacc; __syncthreads();
    for (int off = 512; off > 0; off >>= 1) { if (tid < off) red[tid] += red[tid + off]; __syncthreads(); }
    if (tid == 0) acc_terms[5] = red[0] / (float)H_;
    __syncthreads();

    if (tid == 0) {
        float ce = acc_terms[0] / fmaxf(acc_terms[1], 1.0f);
        out[0] = 1.0f * ce + 0.5f * acc_terms[2] + 0.2f * acc_terms[3]
               + 0.1f * acc_terms[4] + 0.05f * acc_terms[5];
    }
}

// ============================================================
extern "C" void kernel_launch(void* const* d_in, const int* in_sizes, int n_in,
                              void* d_out, int out_size) {
    const float* logits = (const float*)d_in[0];
    const int*   labels = (const int*)  d_in[1];
    const int*   amask  = (const int*)  d_in[2];
    const float* enc    = (const float*)d_in[3];
    const float* dec    = (const float*)d_in[4];
    const float* ln_g_e = (const float*)d_in[5];
    const float* ln_b_e = (const float*)d_in[6];
    const float* W1e    = (const float*)d_in[7];
    const float* b1e    = (const float*)d_in[8];
    const float* W2e    = (const float*)d_in[9];
    const float* b2e    = (const float*)d_in[10];
    const float* ln_g_t = (const float*)d_in[11];
    const float* ln_b_t = (const float*)d_in[12];
    const float* W1t    = (const float*)d_in[13];
    const float* b1t    = (const float*)d_in[14];
    const float* W2t    = (const float*)d_in[15];
    const float* b2t    = (const float*)d_in[16];
    const float* Wb     = (const float*)d_in[17];
    const float* bb     = (const float*)d_in[18];
    float* out = (float*)d_out;

    k_side <<<48,  P_ >>>(enc, dec, amask, labels, Wb, bb,
                          ln_g_e, ln_b_e, W1e, b1e, W2e, b2e,
                          ln_g_t, ln_b_t, W1t, b1t, W2t, b2t);
    k_ce   <<<BT_, 256>>>(logits, labels);
    k_final<<<1,  1024>>>(enc, out);
}